// round 16
// baseline (speedup 1.0000x reference)
#include <cuda_runtime.h>
#include <cuda_bf16.h>
#include <cstdint>

#define B_ROWS 4096
#define N_TOT  8192
#define D_DIM  256
#define INV_T  14.285714285714285714f
#define LOG2E  1.44269504088896340736f
#define LN2    0.69314718055994530942f
#define C1F    ((float)(INV_T * (double)LOG2E))
#define C2F    ((float)((INV_T * (double)LOG2E) / 16129.0))   // /127^2

#define N_CTAS   148
#define N_TILES  2080          // 32*33 + 32*32

// ---------------- device scratch (no allocs allowed) ----------------
__device__ int8_t g_zn[N_TOT * D_DIM];          // quantized normalized rows
__device__ float g_pos[B_ROWS];
__device__ float g_row[16 * N_TOT];             // rowsum partials [(bid&3)*4+wn]
__device__ float g_col[32 * N_TOT];             // colsum partials [d-1]
__device__ float g_part[N_CTAS];                // finalize per-CTA partials
__device__ unsigned int g_cnt;                  // finalize last-CTA counter
__device__ unsigned int g_bcnt[2];              // grid-barrier arrival counters
__device__ volatile unsigned int g_brel[2];     // grid-barrier release gens (monotone)

// ---------------- PTX helpers (compute_100-safe only) ----------------
__device__ __forceinline__ uint32_t smem_u32(const void* p) {
    uint32_t a;
    asm("{ .reg .u64 t; cvta.to.shared.u64 t, %1; cvt.u32.u64 %0, t; }" : "=r"(a) : "l"(p));
    return a;
}
#define CP_ASYNC_CG(sm, gp) \
    asm volatile("cp.async.cg.shared.global [%0], [%1], 16;" :: "r"(sm), "l"(gp))
#define CP_COMMIT()   asm volatile("cp.async.commit_group;" ::: "memory")
#define CP_WAIT_ALL() asm volatile("cp.async.wait_group 0;" ::: "memory")

#define LDSM_X4(r0, r1, r2, r3, addr) \
    asm volatile("ldmatrix.sync.aligned.m8n8.x4.shared.b16 {%0,%1,%2,%3}, [%4];" \
                 : "=r"(r0), "=r"(r1), "=r"(r2), "=r"(r3) : "r"(addr))

__device__ __forceinline__ void mma_s8(int* c, uint32_t a0, uint32_t a1,
                                       uint32_t a2, uint32_t a3,
                                       uint32_t b0, uint32_t b1) {
    asm volatile(
        "mma.sync.aligned.m16n8k32.row.col.s32.s8.s8.s32 "
        "{%0,%1,%2,%3}, {%4,%5,%6,%7}, {%8,%9}, {%0,%1,%2,%3};"
        : "+r"(c[0]), "+r"(c[1]), "+r"(c[2]), "+r"(c[3])
        : "r"(a0), "r"(a1), "r"(a2), "r"(a3), "r"(b0), "r"(b1));
}

__device__ __forceinline__ float expdot(int dot) {
    float f = __int2float_rn(dot);
    float x = fmaf(f, C2F, -C1F);
    float e;
    asm("ex2.approx.f32 %0, %1;" : "=f"(e) : "f"(x));
    return e;
}

__device__ __forceinline__ void tile_rd(int g, int& r, int& d) {
    if (g < 1056) { r = g / 33; d = g - r * 33; }
    else          { int gg = g - 1056; r = 32 + (gg >> 5); d = gg & 31; }
}

// Sense-reversing grid barrier. All 148 CTAs resident (1/SM) -> no deadlock.
// g_brel is monotone across graph replays; g_bcnt resets to 0 each use.
__device__ __forceinline__ void grid_bar(int slot, int tid) {
    __syncthreads();
    if (tid == 0) {
        unsigned gen = g_brel[slot];
        __threadfence();
        unsigned old = atomicAdd(&g_bcnt[slot], 1u);
        if (old == N_CTAS - 1) {
            g_bcnt[slot] = 0;
            __threadfence();
            g_brel[slot] = gen + 1;
        } else {
            while (g_brel[slot] == gen) __nanosleep(64);
        }
        __threadfence();
    }
    __syncthreads();
}

// ---------------------------------------------------------------------------
// SMEM map (sim phase): A0[32K] A1[32K] B0[32K] B1[32K] cb[2][512 floats]
// ---------------------------------------------------------------------------
#define A0_OFF   0u
#define A1_OFF   32768u
#define B0_OFF   65536u
#define B1_OFF   98304u
#define CB_OFF   131072u
#define SMEM_REQ 135168

__device__ __forceinline__ void load_tile512(int rowG, uint32_t dst, int tid) {
#pragma unroll
    for (int p = 0; p < 4; p++) {
        int i = tid + p * 512;
        int chunk = i >> 10, rem = i & 1023, row = rem >> 3, seg = rem & 7;
        const int8_t* g = g_zn + (size_t)(rowG + row) * D_DIM + chunk * 128 + seg * 16;
        uint32_t soff = (uint32_t)(row * 128 + seg * 16);
        soff ^= (soff >> 3) & 0x70;
        CP_ASYNC_CG(dst + chunk * 16384u + soff, g);
    }
}

__global__ void __launch_bounds__(512, 1) fused_kernel(
    const float* __restrict__ zi, const float* __restrict__ zj,
    float* __restrict__ out)
{
    extern __shared__ char dsm[];
    const uint32_t sbase = smem_u32(dsm);
    const int tid = threadIdx.x, wid = tid >> 5, lane = tid & 31;
    const int bid = blockIdx.x;

    // ======================= Phase 0: norm + pos + quantize ================
    {
        const int wg = bid * 16 + wid;          // 0..2367
#pragma unroll 1
        for (int w = wg; w < B_ROWS; w += N_CTAS * 16) {
            const float4* pa = (const float4*)(zi + (size_t)w * D_DIM);
            const float4* pb = (const float4*)(zj + (size_t)w * D_DIM);
            float4 a0 = pa[lane * 2], a1 = pa[lane * 2 + 1];
            float4 b0 = pb[lane * 2], b1 = pb[lane * 2 + 1];
            float sa = a0.x*a0.x + a0.y*a0.y + a0.z*a0.z + a0.w*a0.w
                     + a1.x*a1.x + a1.y*a1.y + a1.z*a1.z + a1.w*a1.w;
            float sb = b0.x*b0.x + b0.y*b0.y + b0.z*b0.z + b0.w*b0.w
                     + b1.x*b1.x + b1.y*b1.y + b1.z*b1.z + b1.w*b1.w;
            float sd = a0.x*b0.x + a0.y*b0.y + a0.z*b0.z + a0.w*b0.w
                     + a1.x*b1.x + a1.y*b1.y + a1.z*b1.z + a1.w*b1.w;
#pragma unroll
            for (int off = 16; off > 0; off >>= 1) {
                sa += __shfl_xor_sync(0xffffffffu, sa, off);
                sb += __shfl_xor_sync(0xffffffffu, sb, off);
                sd += __shfl_xor_sync(0xffffffffu, sd, off);
            }
            float ia = rsqrtf(sa), ib = rsqrtf(sb);
            if (lane == 0) g_pos[w] = sd * ia * ib;
            float qa = ia * 127.0f, qb = ib * 127.0f;
            uint32_t* da = (uint32_t*)(g_zn + (size_t)w * D_DIM);
            uint32_t* db = (uint32_t*)(g_zn + (size_t)(w + B_ROWS) * D_DIM);
#define PK4(x0, x1, x2, x3, s) \
    ( ((uint32_t)(uint8_t)(int8_t)__float2int_rn((x0) * (s)))        | \
      ((uint32_t)(uint8_t)(int8_t)__float2int_rn((x1) * (s)) << 8)   | \
      ((uint32_t)(uint8_t)(int8_t)__float2int_rn((x2) * (s)) << 16)  | \
      ((uint32_t)(uint8_t)(int8_t)__float2int_rn((x3) * (s)) << 24) )
            da[lane * 2 + 0] = PK4(a0.x, a0.y, a0.z, a0.w, qa);
            da[lane * 2 + 1] = PK4(a1.x, a1.y, a1.z, a1.w, qa);
            db[lane * 2 + 0] = PK4(b0.x, b0.y, b0.z, b0.w, qb);
            db[lane * 2 + 1] = PK4(b1.x, b1.y, b1.z, b1.w, qb);
#undef PK4
        }
    }
    grid_bar(0, tid);

    // ======================= Phase 1: sim (R14 body) =======================
    {
        const uint32_t sB[2] = { sbase + B0_OFF, sbase + B1_OFF };
        const uint32_t aSlot[2] = { sbase + A0_OFF, sbase + A1_OFF };
        float* cb = (float*)(dsm + CB_OFF);

        const int wm = wid & 3, wn = wid >> 2;
        const int s = (N_TILES * bid) / N_CTAS;
        const int e = (N_TILES * (bid + 1)) / N_CTAS;

        const int mat = lane >> 3, rowIn = lane & 7;
        const int rsel = (mat & 1) << 3;
        const int ksel = (mat >> 1) << 4;

        const int mA0 = wm * 32 + rsel + rowIn;
        const int nB0 = wn * 32 + rsel + rowIn;
        uint32_t aRow[2], aSw[2], bBase[2], bSw[2];
#pragma unroll
        for (int mt = 0; mt < 2; mt++) {
            int m = mA0 + mt * 16;
            aRow[mt] = (uint32_t)(m * 128);
            aSw[mt] = (uint32_t)((m & 7) << 4);
        }
#pragma unroll
        for (int nt = 0; nt < 2; nt++) {
            int n = nB0 + nt * 16;
            bBase[nt] = (uint32_t)(n * 128);
            bSw[nt] = (uint32_t)((n & 7) << 4);
        }

        uint32_t af[8][2][4];
#define LOAD_AFRAGS(slotBase) do {                                            \
        _Pragma("unroll")                                                     \
        for (int ks = 0; ks < 8; ks++) {                                      \
            const uint32_t chunkOff = (uint32_t)(ks >> 2) * 16384u;           \
            const uint32_t kb = (uint32_t)((ks & 3) * 32 + ksel);             \
            _Pragma("unroll")                                                 \
            for (int mt = 0; mt < 2; mt++)                                    \
                LDSM_X4(af[ks][mt][0], af[ks][mt][1], af[ks][mt][2],          \
                        af[ks][mt][3],                                        \
                        (slotBase) + aRow[mt] + chunkOff + (kb ^ aSw[mt]));   \
        }                                                                     \
    } while (0)

        float rs[2][2] = {{0.f, 0.f}, {0.f, 0.f}};
#define STORE_RS(rr) do {                                                     \
        _Pragma("unroll")                                                     \
        for (int mt = 0; mt < 2; mt++)                                        \
            _Pragma("unroll")                                                 \
            for (int hh = 0; hh < 2; hh++) {                                  \
                float v = rs[mt][hh];                                         \
                v += __shfl_xor_sync(0xffffffffu, v, 1);                      \
                v += __shfl_xor_sync(0xffffffffu, v, 2);                      \
                if ((lane & 3) == 0) {                                        \
                    int row = (rr) * 128 + wm * 32 + mt * 16 + hh * 8 +       \
                              (lane >> 2);                                    \
                    g_row[((bid & 3) * 4 + wn) * N_TOT + row] = v;            \
                }                                                             \
                rs[mt][hh] = 0.f;                                             \
            }                                                                 \
    } while (0)

        int r0, d0; tile_rd(s, r0, d0);
        load_tile512(r0 * 128, aSlot[0], tid);
        load_tile512((((r0 + d0) & 63) * 128), sB[0], tid);
        CP_COMMIT();
        CP_WAIT_ALL();
        __syncthreads();
        LOAD_AFRAGS(aSlot[0]);
        int residentR = r0, curA = 0, buf = 0;

#pragma unroll 1
        for (int g = s; g < e; g++) {
            int r, d; tile_rd(g, r, d);
            const int c = (r + d) & 63;
            const int par = g & 1;
            if (r != residentR) {
                STORE_RS(residentR);
                curA ^= 1;
                LOAD_AFRAGS(aSlot[curA]);
                residentR = r;
            }
            if (g + 1 < e) {
                int rn, dn; tile_rd(g + 1, rn, dn);
                load_tile512((((rn + dn) & 63) * 128), sB[buf ^ 1], tid);
                if (rn != r) load_tile512(rn * 128, aSlot[curA ^ 1], tid);
                CP_COMMIT();
            }

            int acc[2][4][4];
#pragma unroll
            for (int i = 0; i < 2; i++)
#pragma unroll
                for (int j = 0; j < 4; j++)
#pragma unroll
                    for (int q = 0; q < 4; q++) acc[i][j][q] = 0;

            const uint32_t sBt = sB[buf];
#pragma unroll
            for (int ks = 0; ks < 8; ks++) {
                const uint32_t chunkOff = (uint32_t)(ks >> 2) * 16384u;
                const uint32_t kb = (uint32_t)((ks & 3) * 32 + ksel);
#pragma unroll
                for (int nt = 0; nt < 2; nt++) {
                    uint32_t b0, b1, b2, b3;
                    LDSM_X4(b0, b1, b2, b3,
                            sBt + bBase[nt] + chunkOff + (kb ^ bSw[nt]));
#pragma unroll
                    for (int mt = 0; mt < 2; mt++) {
                        mma_s8(acc[mt][2 * nt],     af[ks][mt][0], af[ks][mt][1],
                               af[ks][mt][2], af[ks][mt][3], b0, b2);
                        mma_s8(acc[mt][2 * nt + 1], af[ks][mt][0], af[ks][mt][1],
                               af[ks][mt][2], af[ks][mt][3], b1, b3);
                    }
                }
            }

            const int colT = c * 128 + wn * 32;
            const int rA0 = r * 128 + wm * 32 + (lane >> 2);
            float colp[8];
#pragma unroll
            for (int q = 0; q < 8; q++) colp[q] = 0.f;

#pragma unroll
            for (int mt = 0; mt < 2; mt++) {
                const int rA = rA0 + mt * 16;
                const int rB = rA + 8;
                float s0 = 0.f, s1 = 0.f;
#pragma unroll
                for (int ng = 0; ng < 4; ng++) {
                    const int cg = colT + ng * 8 + ((lane & 3) << 1);
                    float e0 = expdot(acc[mt][ng][0]);
                    float e1 = expdot(acc[mt][ng][1]);
                    float e2 = expdot(acc[mt][ng][2]);
                    float e3 = expdot(acc[mt][ng][3]);
                    if (rA == cg)     e0 = 0.f;
                    if (rA == cg + 1) e1 = 0.f;
                    if (rB == cg)     e2 = 0.f;
                    if (rB == cg + 1) e3 = 0.f;
                    s0 += e0 + e1;
                    s1 += e2 + e3;
                    colp[ng * 2]     += e0 + e2;
                    colp[ng * 2 + 1] += e1 + e3;
                }
                rs[mt][0] += s0;
                rs[mt][1] += s1;
            }

            if (d != 0) {
#pragma unroll
                for (int off = 4; off <= 16; off <<= 1)
#pragma unroll
                    for (int q = 0; q < 8; q++)
                        colp[q] += __shfl_xor_sync(0xffffffffu, colp[q], off);
                const int j = lane >> 2;
                if (j < 4) {
                    float2 v = make_float2(colp[j * 2], colp[j * 2 + 1]);
                    *(float2*)&cb[par * 512 + wm * 128 + wn * 32 + j * 8 +
                                  ((lane & 3) << 1)] = v;
                }
            }

            CP_WAIT_ALL();
            __syncthreads();

            if (d != 0 && wm == 0) {
                float sum = cb[par * 512 + wn * 32 + lane]
                          + cb[par * 512 + 128 + wn * 32 + lane]
                          + cb[par * 512 + 256 + wn * 32 + lane]
                          + cb[par * 512 + 384 + wn * 32 + lane];
                g_col[(size_t)(d - 1) * N_TOT + c * 128 + wn * 32 + lane] = sum;
            }
            buf ^= 1;
        }
        STORE_RS(residentR);
#undef LOAD_AFRAGS
#undef STORE_RS
    }
    grid_bar(1, tid);

    // ======================= Phase 2: finalize =============================
    {
        float* sd = (float*)dsm;              // reuse smem (sim phase done)
        __shared__ bool amLast;
        const int start = (N_TOT * bid) / N_CTAS;
        const int end   = (N_TOT * (bid + 1)) / N_CTAS;   // 55 or 56 rows
        float term = 0.f;
        if (tid < end - start) {
            int row = start + tid;
            float S = 0.f;
#pragma unroll
            for (int q = 0; q < 16; q++) S += g_row[q * N_TOT + row];
#pragma unroll 8
            for (int q = 0; q < 32; q++) S += g_col[q * N_TOT + row];
            float l;
            asm("lg2.approx.f32 %0, %1;" : "=f"(l) : "f"(S));
            term = INV_T + LN2 * l - g_pos[row & (B_ROWS - 1)] * INV_T;
        }
        sd[tid] = term;
        __syncthreads();
        for (int o = 256; o > 0; o >>= 1) {
            if (tid < o) sd[tid] += sd[tid + o];
            __syncthreads();
        }
        if (tid == 0) {
            g_part[bid] = sd[0];
            __threadfence();
            unsigned prev = atomicAdd(&g_cnt, 1u);
            amLast = (prev == N_CTAS - 1);
        }
        __syncthreads();
        if (amLast) {
            float v = (tid < N_CTAS) ? g_part[tid] : 0.f;
            sd[tid] = v;
            __syncthreads();
            for (int o = 256; o > 0; o >>= 1) {
                if (tid < o) sd[tid] += sd[tid + o];
                __syncthreads();
            }
            if (tid == 0) {
                out[0] = sd[0] * (1.0f / (float)N_TOT);
                g_cnt = 0u;   // reset for next graph replay
            }
        }
    }
}

// ---------------------------------------------------------------------------
extern "C" void kernel_launch(void* const* d_in, const int* in_sizes, int n_in,
                              void* d_out, int out_size) {
    (void)in_sizes; (void)n_in; (void)out_size;
    const float* zi = (const float*)d_in[0];
    const float* zj = (const float*)d_in[1];

    cudaFuncSetAttribute(fused_kernel, cudaFuncAttributeMaxDynamicSharedMemorySize,
                         SMEM_REQ);
    fused_kernel<<<N_CTAS, 512, SMEM_REQ>>>(zi, zj, (float*)d_out);
}

// round 17
// speedup vs baseline: 1.1393x; 1.1393x over previous
#include <cuda_runtime.h>
#include <cuda_bf16.h>
#include <cstdint>

#define B_ROWS 4096
#define N_TOT  8192
#define D_DIM  256
#define INV_T  14.285714285714285714f
#define LOG2E  1.44269504088896340736f
#define LN2    0.69314718055994530942f
#define C1F    ((float)(INV_T * (double)LOG2E))
#define C2F    ((float)((INV_T * (double)LOG2E) / 16129.0))   // /127^2

#define N_CTAS   148
#define N_TILES  2080          // 32*33 + 32*32

// ---------------- device scratch (no allocs allowed) ----------------
__device__ int8_t g_zn[N_TOT * D_DIM];          // quantized normalized rows, 2MB
__device__ float g_pos[B_ROWS];
__device__ float g_row[16 * N_TOT];             // rowsum partials [(bid&3)*4+wn]
__device__ float g_col[32 * N_TOT];             // colsum partials [d-1] (wm-combined)
__device__ float g_part[64];                    // finalize block partials
__device__ unsigned int g_cnt;                  // finalize last-block counter

// ---------------- PTX helpers (compute_100-safe only) ----------------
__device__ __forceinline__ uint32_t smem_u32(const void* p) {
    uint32_t a;
    asm("{ .reg .u64 t; cvta.to.shared.u64 t, %1; cvt.u32.u64 %0, t; }" : "=r"(a) : "l"(p));
    return a;
}
#define CP_ASYNC_CG(sm, gp) \
    asm volatile("cp.async.cg.shared.global [%0], [%1], 16;" :: "r"(sm), "l"(gp))
#define CP_COMMIT()   asm volatile("cp.async.commit_group;" ::: "memory")
#define CP_WAIT_ALL() asm volatile("cp.async.wait_group 0;" ::: "memory")

#define LDSM_X4(r0, r1, r2, r3, addr) \
    asm volatile("ldmatrix.sync.aligned.m8n8.x4.shared.b16 {%0,%1,%2,%3}, [%4];" \
                 : "=r"(r0), "=r"(r1), "=r"(r2), "=r"(r3) : "r"(addr))

// s8 x s8 -> s32, m16n8k32
__device__ __forceinline__ void mma_s8(int* c, uint32_t a0, uint32_t a1,
                                       uint32_t a2, uint32_t a3,
                                       uint32_t b0, uint32_t b1) {
    asm volatile(
        "mma.sync.aligned.m16n8k32.row.col.s32.s8.s8.s32 "
        "{%0,%1,%2,%3}, {%4,%5,%6,%7}, {%8,%9}, {%0,%1,%2,%3};"
        : "+r"(c[0]), "+r"(c[1]), "+r"(c[2]), "+r"(c[3])
        : "r"(a0), "r"(a1), "r"(a2), "r"(a3), "r"(b0), "r"(b1));
}

__device__ __forceinline__ float expdot(int dot) {
    float f = __int2float_rn(dot);
    float x = fmaf(f, C2F, -C1F);
    float e;
    asm("ex2.approx.f32 %0, %1;" : "=f"(e) : "f"(x));
    return e;
}

// global tile index -> (r, d); list ordered by r, d. r<32: d in 0..32; else 0..31
__device__ __forceinline__ void tile_rd(int g, int& r, int& d) {
    if (g < 1056) { r = g / 33; d = g - r * 33; }
    else          { int gg = g - 1056; r = 32 + (gg >> 5); d = gg & 31; }
}

// ---------------------------------------------------------------------------
// 1) Fused normalize + pos + int8 quantize
// ---------------------------------------------------------------------------
__global__ void norm_pos_kernel(const float* __restrict__ zi,
                                const float* __restrict__ zj) {
    int w = (blockIdx.x * blockDim.x + threadIdx.x) >> 5;
    int lane = threadIdx.x & 31;
    if (w >= B_ROWS) return;
    const float4* pa = (const float4*)(zi + (size_t)w * D_DIM);
    const float4* pb = (const float4*)(zj + (size_t)w * D_DIM);
    float4 a0 = pa[lane * 2], a1 = pa[lane * 2 + 1];
    float4 b0 = pb[lane * 2], b1 = pb[lane * 2 + 1];
    float sa = a0.x*a0.x + a0.y*a0.y + a0.z*a0.z + a0.w*a0.w
             + a1.x*a1.x + a1.y*a1.y + a1.z*a1.z + a1.w*a1.w;
    float sb = b0.x*b0.x + b0.y*b0.y + b0.z*b0.z + b0.w*b0.w
             + b1.x*b1.x + b1.y*b1.y + b1.z*b1.z + b1.w*b1.w;
    float sd = a0.x*b0.x + a0.y*b0.y + a0.z*b0.z + a0.w*b0.w
             + a1.x*b1.x + a1.y*b1.y + a1.z*b1.z + a1.w*b1.w;
#pragma unroll
    for (int off = 16; off > 0; off >>= 1) {
        sa += __shfl_xor_sync(0xffffffffu, sa, off);
        sb += __shfl_xor_sync(0xffffffffu, sb, off);
        sd += __shfl_xor_sync(0xffffffffu, sd, off);
    }
    float ia = rsqrtf(sa), ib = rsqrtf(sb);
    if (lane == 0) g_pos[w] = sd * ia * ib;
    float qa = ia * 127.0f, qb = ib * 127.0f;

    uint32_t* da = (uint32_t*)(g_zn + (size_t)w * D_DIM);
    uint32_t* db = (uint32_t*)(g_zn + (size_t)(w + B_ROWS) * D_DIM);
#define PK4(x0, x1, x2, x3, s) \
    ( ((uint32_t)(uint8_t)(int8_t)__float2int_rn((x0) * (s)))        | \
      ((uint32_t)(uint8_t)(int8_t)__float2int_rn((x1) * (s)) << 8)   | \
      ((uint32_t)(uint8_t)(int8_t)__float2int_rn((x2) * (s)) << 16)  | \
      ((uint32_t)(uint8_t)(int8_t)__float2int_rn((x3) * (s)) << 24) )
    da[lane * 2 + 0] = PK4(a0.x, a0.y, a0.z, a0.w, qa);
    da[lane * 2 + 1] = PK4(a1.x, a1.y, a1.z, a1.w, qa);
    db[lane * 2 + 0] = PK4(b0.x, b0.y, b0.z, b0.w, qb);
    db[lane * 2 + 1] = PK4(b1.x, b1.y, b1.z, b1.w, qb);
#undef PK4
}

// ---------------------------------------------------------------------------
// 2) Symmetric fused int8-IMMA GEMM, 148 CTAs (R14 base, proven 53.3us) with
// epilogue specialized on block-uniform d: off-diagonal tiles skip the 32
// diagonal compares/selects; the d==0 tile skips all colsum work.
// SMEM: A0[32K] A1[32K] B0[32K] B1[32K] cb[2][512 floats]
// ---------------------------------------------------------------------------
#define A0_OFF   0u
#define A1_OFF   32768u
#define B0_OFF   65536u
#define B1_OFF   98304u
#define CB_OFF   131072u
#define SMEM_REQ 135168

__device__ __forceinline__ void load_tile512(int rowG, uint32_t dst, int tid) {
#pragma unroll
    for (int p = 0; p < 4; p++) {
        int i = tid + p * 512;                 // 0..2047 16B units
        int chunk = i >> 10, rem = i & 1023, row = rem >> 3, seg = rem & 7;
        const int8_t* g = g_zn + (size_t)(rowG + row) * D_DIM + chunk * 128 + seg * 16;
        uint32_t soff = (uint32_t)(row * 128 + seg * 16);
        soff ^= (soff >> 3) & 0x70;
        CP_ASYNC_CG(dst + chunk * 16384u + soff, g);
    }
}

__global__ void __launch_bounds__(512, 1) sim_kernel() {
    extern __shared__ char dsm[];
    const uint32_t sbase = smem_u32(dsm);
    const uint32_t sB[2] = { sbase + B0_OFF, sbase + B1_OFF };
    const uint32_t aSlot[2] = { sbase + A0_OFF, sbase + A1_OFF };
    float* cb = (float*)(dsm + CB_OFF);        // [par][wm][wn][32]

    const int tid = threadIdx.x, wid = tid >> 5, lane = tid & 31;
    const int wm = wid & 3, wn = wid >> 2;     // 4 x 4 warp grid
    const int bid = blockIdx.x;

    const int s = (N_TILES * bid) / N_CTAS;
    const int e = (N_TILES * (bid + 1)) / N_CTAS;

    const int mat = lane >> 3, rowIn = lane & 7;
    const int rsel = (mat & 1) << 3;
    const int ksel = (mat >> 1) << 4;          // +0/+16 BYTES along k

    const int mA0 = wm * 32 + rsel + rowIn;
    const int nB0 = wn * 32 + rsel + rowIn;
    uint32_t aRow[2], aSw[2], bBase[2], bSw[2];
#pragma unroll
    for (int mt = 0; mt < 2; mt++) {
        int m = mA0 + mt * 16;
        aRow[mt] = (uint32_t)(m * 128);
        aSw[mt] = (uint32_t)((m & 7) << 4);
    }
#pragma unroll
    for (int nt = 0; nt < 2; nt++) {
        int n = nB0 + nt * 16;
        bBase[nt] = (uint32_t)(n * 128);
        bSw[nt] = (uint32_t)((n & 7) << 4);
    }

    uint32_t af[8][2][4];                      // A fragments, full k=256
#define LOAD_AFRAGS(slotBase) do {                                            \
        _Pragma("unroll")                                                     \
        for (int ks = 0; ks < 8; ks++) {                                      \
            const uint32_t chunkOff = (uint32_t)(ks >> 2) * 16384u;           \
            const uint32_t kb = (uint32_t)((ks & 3) * 32 + ksel);             \
            _Pragma("unroll")                                                 \
            for (int mt = 0; mt < 2; mt++)                                    \
                LDSM_X4(af[ks][mt][0], af[ks][mt][1], af[ks][mt][2],          \
                        af[ks][mt][3],                                        \
                        (slotBase) + aRow[mt] + chunkOff + (kb ^ aSw[mt]));   \
        }                                                                     \
    } while (0)

    float rs[2][2] = {{0.f, 0.f}, {0.f, 0.f}};
#define STORE_RS(rr) do {                                                     \
        _Pragma("unroll")                                                     \
        for (int mt = 0; mt < 2; mt++)                                        \
            _Pragma("unroll")                                                 \
            for (int hh = 0; hh < 2; hh++) {                                  \
                float v = rs[mt][hh];                                         \
                v += __shfl_xor_sync(0xffffffffu, v, 1);                      \
                v += __shfl_xor_sync(0xffffffffu, v, 2);                      \
                if ((lane & 3) == 0) {                                        \
                    int row = (rr) * 128 + wm * 32 + mt * 16 + hh * 8 +       \
                              (lane >> 2);                                    \
                    g_row[((bid & 3) * 4 + wn) * N_TOT + row] = v;            \
                }                                                             \
                rs[mt][hh] = 0.f;                                             \
            }                                                                 \
    } while (0)

    // Prologue
    int r0, d0; tile_rd(s, r0, d0);
    load_tile512(r0 * 128, aSlot[0], tid);
    load_tile512((((r0 + d0) & 63) * 128), sB[0], tid);
    CP_COMMIT();
    CP_WAIT_ALL();
    __syncthreads();
    LOAD_AFRAGS(aSlot[0]);
    int residentR = r0, curA = 0, buf = 0;

#pragma unroll 1
    for (int g = s; g < e; g++) {
        int r, d; tile_rd(g, r, d);
        const int c = (r + d) & 63;
        const int par = g & 1;
        if (r != residentR) {                  // segment switch (<=1 per CTA)
            STORE_RS(residentR);
            curA ^= 1;
            LOAD_AFRAGS(aSlot[curA]);
            residentR = r;
        }
        if (g + 1 < e) {                       // prefetch next tile
            int rn, dn; tile_rd(g + 1, rn, dn);
            load_tile512((((rn + dn) & 63) * 128), sB[buf ^ 1], tid);
            if (rn != r) load_tile512(rn * 128, aSlot[curA ^ 1], tid);
            CP_COMMIT();
        }

        int acc[2][4][4];
#pragma unroll
        for (int i = 0; i < 2; i++)
#pragma unroll
            for (int j = 0; j < 4; j++)
#pragma unroll
                for (int q = 0; q < 4; q++) acc[i][j][q] = 0;

        const uint32_t sBt = sB[buf];
#pragma unroll
        for (int ks = 0; ks < 8; ks++) {
            const uint32_t chunkOff = (uint32_t)(ks >> 2) * 16384u;
            const uint32_t kb = (uint32_t)((ks & 3) * 32 + ksel);
#pragma unroll
            for (int nt = 0; nt < 2; nt++) {
                uint32_t b0, b1, b2, b3;
                LDSM_X4(b0, b1, b2, b3,
                        sBt + bBase[nt] + chunkOff + (kb ^ bSw[nt]));
#pragma unroll
                for (int mt = 0; mt < 2; mt++) {
                    mma_s8(acc[mt][2 * nt],     af[ks][mt][0], af[ks][mt][1],
                           af[ks][mt][2], af[ks][mt][3], b0, b2);
                    mma_s8(acc[mt][2 * nt + 1], af[ks][mt][0], af[ks][mt][1],
                           af[ks][mt][2], af[ks][mt][3], b1, b3);
                }
            }
        }

        // Epilogue, specialized on block-uniform d.
        const int colT = c * 128 + wn * 32;
        if (d != 0) {
            // Off-diagonal: no diagonal possible -> no compares.
            float colp[8];
#pragma unroll
            for (int q = 0; q < 8; q++) colp[q] = 0.f;
#pragma unroll
            for (int mt = 0; mt < 2; mt++) {
                float s0 = 0.f, s1 = 0.f;
#pragma unroll
                for (int ng = 0; ng < 4; ng++) {
                    float e0 = expdot(acc[mt][ng][0]);
                    float e1 = expdot(acc[mt][ng][1]);
                    float e2 = expdot(acc[mt][ng][2]);
                    float e3 = expdot(acc[mt][ng][3]);
                    s0 += e0 + e1;
                    s1 += e2 + e3;
                    colp[ng * 2]     += e0 + e2;
                    colp[ng * 2 + 1] += e1 + e3;
                }
                rs[mt][0] += s0;
                rs[mt][1] += s1;
            }
            // butterfly over the 8 row-groups; stage into cb[par]
#pragma unroll
            for (int off = 4; off <= 16; off <<= 1)
#pragma unroll
                for (int q = 0; q < 8; q++)
                    colp[q] += __shfl_xor_sync(0xffffffffu, colp[q], off);
            const int j = lane >> 2;
            if (j < 4) {
                float2 v = make_float2(colp[j * 2], colp[j * 2 + 1]);
                *(float2*)&cb[par * 512 + wm * 128 + wn * 32 + j * 8 +
                              ((lane & 3) << 1)] = v;
            }
        } else {
            // Diagonal tile: compares needed, colsum discarded entirely.
            const int rA0 = r * 128 + wm * 32 + (lane >> 2);
#pragma unroll
            for (int mt = 0; mt < 2; mt++) {
                const int rA = rA0 + mt * 16;
                const int rB = rA + 8;
                float s0 = 0.f, s1 = 0.f;
#pragma unroll
                for (int ng = 0; ng < 4; ng++) {
                    const int cg = colT + ng * 8 + ((lane & 3) << 1);
                    float e0 = expdot(acc[mt][ng][0]);
                    float e1 = expdot(acc[mt][ng][1]);
                    float e2 = expdot(acc[mt][ng][2]);
                    float e3 = expdot(acc[mt][ng][3]);
                    if (rA == cg)     e0 = 0.f;
                    if (rA == cg + 1) e1 = 0.f;
                    if (rB == cg)     e2 = 0.f;
                    if (rB == cg + 1) e3 = 0.f;
                    s0 += e0 + e1;
                    s1 += e2 + e3;
                }
                rs[mt][0] += s0;
                rs[mt][1] += s1;
            }
        }

        // ONE barrier per tile: next-B residency + cb[par] visibility.
        CP_WAIT_ALL();
        __syncthreads();

        if (d != 0 && wm == 0) {
            // combine the 4 wm parts while other warps start the next k-loop.
            float sum = cb[par * 512 + wn * 32 + lane]
                      + cb[par * 512 + 128 + wn * 32 + lane]
                      + cb[par * 512 + 256 + wn * 32 + lane]
                      + cb[par * 512 + 384 + wn * 32 + lane];
            g_col[(size_t)(d - 1) * N_TOT + c * 128 + wn * 32 + lane] = sum;
        }
        buf ^= 1;
    }
    STORE_RS(residentR);
#undef LOAD_AFRAGS
#undef STORE_RS
}

// ---------------------------------------------------------------------------
// 3) finalize (single kernel, last-block reduction, graph-replay-safe)
// ---------------------------------------------------------------------------
__global__ void finalize_kernel(float* __restrict__ out) {
    __shared__ float sd[128];
    __shared__ bool amLast;
    const int tid = threadIdx.x;
    const int row = blockIdx.x * 128 + tid;
    float S = 0.f;
#pragma unroll
    for (int s = 0; s < 16; s++) S += g_row[s * N_TOT + row];
#pragma unroll 8
    for (int s = 0; s < 32; s++) S += g_col[s * N_TOT + row];
    float l;
    asm("lg2.approx.f32 %0, %1;" : "=f"(l) : "f"(S));
    float term = INV_T + LN2 * l - g_pos[row & (B_ROWS - 1)] * INV_T;
    sd[tid] = term;
    __syncthreads();
    for (int o = 64; o > 0; o >>= 1) {
        if (tid < o) sd[tid] += sd[tid + o];
        __syncthreads();
    }
    if (tid == 0) {
        g_part[blockIdx.x] = sd[0];
        __threadfence();
        unsigned int prev = atomicAdd(&g_cnt, 1u);
        amLast = (prev == 63u);
    }
    __syncthreads();
    if (amLast) {
        if (tid < 32) {
            float v = g_part[tid] + g_part[tid + 32];
#pragma unroll
            for (int off = 16; off > 0; off >>= 1)
                v += __shfl_xor_sync(0xffffffffu, v, off);
            if (tid == 0) {
                out[0] = v * (1.0f / (float)N_TOT);
                g_cnt = 0u;   // reset for next graph replay
            }
        }
    }
}

// ---------------------------------------------------------------------------
extern "C" void kernel_launch(void* const* d_in, const int* in_sizes, int n_in,
                              void* d_out, int out_size) {
    (void)in_sizes; (void)n_in; (void)out_size;
    const float* zi = (const float*)d_in[0];
    const float* zj = (const float*)d_in[1];

    cudaFuncSetAttribute(sim_kernel, cudaFuncAttributeMaxDynamicSharedMemorySize,
                         SMEM_REQ);
    norm_pos_kernel<<<1024, 128>>>(zi, zj);
    sim_kernel<<<N_CTAS, 512, SMEM_REQ>>>();
    finalize_kernel<<<64, 128>>>((float*)d_out);
}